// round 5
// baseline (speedup 1.0000x reference)
#include <cuda_runtime.h>
#include <math.h>

#define NK 10
#define APW 544     // padded A row width (y+128 valid for y in [-128, 415])
#define CHUNK 32    // dx rows per partial-conv block
#define MAXCH 8     // ceil(255/32)
#define AP2W 416    // packed-pair A row width (pairs)
#define AP2B 136    // base offset (pair index of logical y=0), even => 16B alignment

typedef unsigned long long u64;

// ---------------- scratch (static device globals; no allocation) ----------------
__device__ __align__(16) float  g_Apad[3][256][APW]; // planar A, y wrapped: [c][x][y+128]
__device__ __align__(16) float  g_Asum[256][256];
__device__ __align__(16) u64    g_Ap2[3][256][AP2W]; // packed pairs: (A[y], A[y+128])
__device__ __align__(16) float  g_Kp[NK][257][512];  // packed dup kernels: [k][dx+128][2*(dy+128)+{0,1}]; row 256 = zero pad
__device__ double g_part[NK][256];
__device__ double g_ksum[NK];
__device__ int    g_rad[NK];
__device__ int    g_nch[NK];
__device__ __align__(16) float  g_pc[NK][MAXCH][256][256];  // partial conv sums (20MB)
__device__ __align__(16) float  g_U3[3][256][256];
__device__ __align__(16) float  g_mu[256*256*6];

__constant__ int c_C0[NK]  = {0,0,0,1,1,1,2,2,2,0};
__constant__ int c_grp[NK] = {0,0,0,1,1,1,2,2,2,0};

// ---------------- packed-f32x2 helpers ----------------
__device__ __forceinline__ u64 pk(float lo, float hi) {
    u64 r; asm("mov.b64 %0, {%1, %2};" : "=l"(r) : "f"(lo), "f"(hi)); return r;
}
__device__ __forceinline__ void fma2(u64 &d, u64 a, u64 b) {
    asm("fma.rn.f32x2 %0, %1, %2, %0;" : "+l"(d) : "l"(a), "l"(b));
}
__device__ __forceinline__ float2 upk(u64 v) {
    float2 f; asm("mov.b64 {%0, %1}, %2;" : "=f"(f.x), "=f"(f.y) : "l"(v)); return f;
}

// ---------------- 1. prep: planar padded A, packed pairs, Asum, radii ----------------
__global__ void prep_kernel(const float* __restrict__ A,
                            const float* __restrict__ R,
                            const float* __restrict__ r) {
    int x = blockIdx.x, y = threadIdx.x;
    float a0 = A[(x*256+y)*3+0];
    float a1 = A[(x*256+y)*3+1];
    float a2 = A[(x*256+y)*3+2];
    g_Asum[x][y] = a0 + a1 + a2;
    for (int j = y; j < APW; j += 256) {
        int src = (j - 128) & 255;
        g_Apad[0][x][j] = A[(x*256+src)*3+0];
        g_Apad[1][x][j] = A[(x*256+src)*3+1];
        g_Apad[2][x][j] = A[(x*256+src)*3+2];
    }
    for (int p = y; p < AP2W; p += 256) {
        int lo = (p - AP2B) & 255;
        int hi = (p - AP2B + 128) & 255;
        g_Ap2[0][x][p] = pk(A[(x*256+lo)*3+0], A[(x*256+hi)*3+0]);
        g_Ap2[1][x][p] = pk(A[(x*256+lo)*3+1], A[(x*256+hi)*3+1]);
        g_Ap2[2][x][p] = pk(A[(x*256+lo)*3+2], A[(x*256+hi)*3+2]);
    }
    if (x == 0 && y < NK) {
        // sig = 0.5*(tanh(-(Dk-1)*5)+1) underflows to exactly 0 past Dk~2.8.
        float rc = 2.85f * (R[0] + 15.0f) * r[y];
        int rad = (int)rc + 1;
        rad = max(1, min(127, rad));
        g_rad[y] = rad;
        g_nch[y] = (2*rad + 1 + CHUNK - 1) / CHUNK;
    }
}

// ---------------- 2. build packed kernels + per-row double sums ----------------
__global__ void kbuild_kernel(const float* __restrict__ R,
                              const float* __restrict__ r,
                              const float* __restrict__ a,
                              const float* __restrict__ b,
                              const float* __restrict__ w) {
    int i = blockIdx.x;   // dx + 128, or 256 = pad row
    int k = blockIdx.y;
    int j = threadIdx.x;  // dy + 128
    if (i == 256) {       // zero pad row (read by 4-tap overrun of last row)
        g_Kp[k][256][2*j]   = 0.0f;
        g_Kp[k][256][2*j+1] = 0.0f;
        return;
    }
    float fdx = (float)(i - 128);
    float fdy = (float)(j - 128);
    float D  = sqrtf(fdx*fdx + fdy*fdy);
    float Dk = D / ((R[0] + 15.0f) * r[k]);
    float val = 0.0f;
    if (Dk < 2.9f) {   // sig is exactly 0 (fp32 tanh saturation) past ~2.8
        float ker = 0.0f;
        #pragma unroll
        for (int t = 0; t < 3; t++) {
            float d = Dk - a[k*3+t];
            ker += b[k*3+t] * expf(-d*d / w[k*3+t]);
        }
        float sig = 0.5f * (tanhf(-(Dk - 1.0f) * 5.0f) + 1.0f);
        val = sig * ker;
    }
    g_Kp[k][i][2*j]   = val;
    g_Kp[k][i][2*j+1] = val;

    __shared__ double sd[256];
    sd[j] = (double)val;
    __syncthreads();
    for (int s = 128; s > 0; s >>= 1) {
        if (j < s) sd[j] += sd[j + s];
        __syncthreads();
    }
    if (j == 0) g_part[k][i] = sd[0];
}

// ---------------- 3. reduce row sums -> ksum (deterministic) ----------------
__global__ void ksum_kernel() {
    int k = blockIdx.x, j = threadIdx.x;
    __shared__ double sd[256];
    sd[j] = g_part[k][j];
    __syncthreads();
    for (int s = 128; s > 0; s >>= 1) {
        if (j < s) sd[j] += sd[j + s];
        __syncthreads();
    }
    if (j == 0) g_ksum[k] = sd[0];
}

// ---------------- 4. partial circular conv (pair-packed f32x2, dx-chunked) ----------------
// Pair lane q of f32x2 = outputs (y, y+128): same K taps, A pairs pre-packed.
// out[y] = sum_dx sum_u K[dx][u] * A[x-dx][y+u]  (K symmetric in u).
__global__ void __launch_bounds__(128, 8) convp_kernel() {
    int k  = blockIdx.x;
    int ch = blockIdx.y;
    int rad = g_rad[k];
    if (ch >= g_nch[k]) return;

    int x    = blockIdx.z * 4 + threadIdx.y;
    int c    = c_C0[k];
    int y0   = threadIdx.x << 2;     // outputs y0..y0+3 (lo) and +128 (hi)

    int dx0 = -rad + ch * CHUNK;
    int dx1 = min(rad, dx0 + CHUNK - 1);

    const u64* __restrict__ Ap = &g_Ap2[c][0][0];
    const u64* __restrict__ Kp = (const u64*)&g_Kp[k][0][0];

    float aL0=0.f,aL1=0.f,aL2=0.f,aL3=0.f;
    float aH0=0.f,aH1=0.f,aH2=0.f,aH3=0.f;

    for (int dx = dx0; dx <= dx1; ++dx) {
        const u64* __restrict__ Ar = Ap + ((x - dx) & 255) * AP2W + AP2B + y0;
        const u64* __restrict__ Kr = Kp + (dx + 128) * 256 + 128;

        int rr = rad*rad - dx*dx;
        int radY = min(127, __float2int_rz(sqrtf((float)rr)) + 1);
        int us = -((radY + 3) & ~3);          // aligned start, covers [-radY, radY]

        u64 c0=0ull, c1=0ull, c2=0ull, c3=0ull;

        ulonglong2 w0 = *(const ulonglong2*)(Ar + us);      // pairs u, u+1
        ulonglong2 w1 = *(const ulonglong2*)(Ar + us + 2);  // pairs u+2, u+3
        ulonglong2 w2 = *(const ulonglong2*)(Ar + us + 4);
        ulonglong2 w3 = *(const ulonglong2*)(Ar + us + 6);

        #pragma unroll 2
        for (int u = us; u <= radY; u += 4) {
            ulonglong2 kA = *(const ulonglong2*)(Kr + u);      // taps u, u+1
            ulonglong2 kB = *(const ulonglong2*)(Kr + u + 2);  // taps u+2, u+3

            fma2(c0, kA.x, w0.x); fma2(c1, kA.x, w0.y); fma2(c2, kA.x, w1.x); fma2(c3, kA.x, w1.y);
            fma2(c0, kA.y, w0.y); fma2(c1, kA.y, w1.x); fma2(c2, kA.y, w1.y); fma2(c3, kA.y, w2.x);
            fma2(c0, kB.x, w1.x); fma2(c1, kB.x, w1.y); fma2(c2, kB.x, w2.x); fma2(c3, kB.x, w2.y);
            fma2(c0, kB.y, w1.y); fma2(c1, kB.y, w2.x); fma2(c2, kB.y, w2.y); fma2(c3, kB.y, w3.x);

            w0 = w2; w1 = w3;
            w2 = *(const ulonglong2*)(Ar + u + 8);
            w3 = *(const ulonglong2*)(Ar + u + 10);
        }

        float2 r0 = upk(c0), r1 = upk(c1), r2 = upk(c2), r3 = upk(c3);
        aL0 += r0.x; aL1 += r1.x; aL2 += r2.x; aL3 += r3.x;
        aH0 += r0.y; aH1 += r1.y; aH2 += r2.y; aH3 += r3.y;
    }

    *(float4*)&g_pc[k][ch][x][y0]       = make_float4(aL0, aL1, aL2, aL3);
    *(float4*)&g_pc[k][ch][x][y0 + 128] = make_float4(aH0, aH1, aH2, aH3);
}

// ---------------- 5. combine partials + growth + channel-group sums ----------------
__global__ void combine_kernel(const float* __restrict__ m,
                               const float* __restrict__ s,
                               const float* __restrict__ h) {
    int x = blockIdx.x, y = threadIdx.x;
    float u0 = 0.f, u1 = 0.f, u2 = 0.f;
    #pragma unroll
    for (int k = 0; k < NK; k++) {
        int nch = g_nch[k];
        double acc = 0.0;
        for (int ch = 0; ch < nch; ch++)
            acc += (double)g_pc[k][ch][x][y];
        float U  = (float)(acc / g_ksum[k]);
        float gg = (U - m[k]) / s[k];
        float gr = (expf(-0.5f * gg * gg) * 2.0f - 1.0f) * h[k];
        int grp = c_grp[k];
        if (grp == 0) u0 += gr;
        else if (grp == 1) u1 += gr;
        else u2 += gr;
    }
    g_U3[0][x][y] = u0;
    g_U3[1][x][y] = u1;
    g_U3[2][x][y] = u2;
}

// ---------------- 6. sobel + flow F + mu ----------------
__device__ __forceinline__ float padv(const float* p, int xx, int yy) {
    return (xx >= 0 && xx < 256 && yy >= 0 && yy < 256) ? p[xx*256 + yy] : 0.0f;
}

__global__ void sobelmu_kernel(const float* __restrict__ A) {
    int x = blockIdx.x, y = threadIdx.x;
    const float* As = &g_Asum[0][0];
    float nA0 = (padv(As,x-1,y-1) + 2.0f*padv(As,x-1,y) + padv(As,x-1,y+1))
              - (padv(As,x+1,y-1) + 2.0f*padv(As,x+1,y) + padv(As,x+1,y+1));
    float nA1 = (padv(As,x-1,y-1) + 2.0f*padv(As,x,y-1) + padv(As,x+1,y-1))
              - (padv(As,x-1,y+1) + 2.0f*padv(As,x,y+1) + padv(As,x+1,y+1));

    float px = (float)x + 0.5f;
    float py = (float)y + 0.5f;
    #pragma unroll
    for (int c = 0; c < 3; c++) {
        const float* Uc = &g_U3[c][0][0];
        float nU0 = (padv(Uc,x-1,y-1) + 2.0f*padv(Uc,x-1,y) + padv(Uc,x-1,y+1))
                  - (padv(Uc,x+1,y-1) + 2.0f*padv(Uc,x+1,y) + padv(Uc,x+1,y+1));
        float nU1 = (padv(Uc,x-1,y-1) + 2.0f*padv(Uc,x,y-1) + padv(Uc,x+1,y-1))
                  - (padv(Uc,x-1,y+1) + 2.0f*padv(Uc,x,y+1) + padv(Uc,x+1,y+1));
        float Ac = A[(x*256+y)*3 + c];
        float al = Ac * (1.0f/3.0f);
        al = al * al;
        al = fminf(al, 1.0f);
        float F0 = nU0 * (1.0f - al) - nA0 * al;
        float F1 = nU1 * (1.0f - al) - nA1 * al;
        float d0 = fminf(fmaxf(0.2f * F0, -4.35f), 4.35f);
        float d1 = fminf(fmaxf(0.2f * F1, -4.35f), 4.35f);
        float mux = fminf(fmaxf(px + d0, 0.65f), 255.35f);
        float muy = fminf(fmaxf(py + d1, 0.65f), 255.35f);
        g_mu[(x*256+y)*6 + c*2 + 0] = mux;
        g_mu[(x*256+y)*6 + c*2 + 1] = muy;
    }
}

// ---------------- 7. reintegration tracking (gather form) ----------------
__global__ void gather_kernel(float* __restrict__ out) {
    int x = blockIdx.x, y = threadIdx.x;
    float px = (float)x + 0.5f;
    float py = (float)y + 0.5f;
    float acc0 = 0.0f, acc1 = 0.0f, acc2 = 0.0f;
    const float inv = 1.0f / 1.69f;   // 1/(4*sigma^2)

    #pragma unroll
    for (int dx = -5; dx <= 5; ++dx) {
        int i = (x - dx) & 255;
        #pragma unroll
        for (int dy = -5; dy <= 5; ++dy) {
            int j = (y - dy) & 255;
            const float* mu = g_mu + (i*256 + j)*6;
            #pragma unroll
            for (int c = 0; c < 3; c++) {
                float ax = 1.15f - fabsf(px - mu[2*c + 0]);
                float ay = 1.15f - fabsf(py - mu[2*c + 1]);
                ax = fminf(fmaxf(ax, 0.0f), 1.0f);
                ay = fminf(fmaxf(ay, 0.0f), 1.0f);
                float area = ax * ay * inv;
                float av = g_Apad[c][i][j + 128];
                if (c == 0) acc0 = fmaf(av, area, acc0);
                else if (c == 1) acc1 = fmaf(av, area, acc1);
                else acc2 = fmaf(av, area, acc2);
            }
        }
    }
    out[(x*256+y)*3 + 0] = acc0;
    out[(x*256+y)*3 + 1] = acc1;
    out[(x*256+y)*3 + 2] = acc2;
}

// ---------------- launch ----------------
extern "C" void kernel_launch(void* const* d_in, const int* in_sizes, int n_in,
                              void* d_out, int out_size) {
    const float* A = (const float*)d_in[0];
    const float* R = (const float*)d_in[1];
    const float* r = (const float*)d_in[2];
    const float* m = (const float*)d_in[3];
    const float* s = (const float*)d_in[4];
    const float* h = (const float*)d_in[5];
    const float* a = (const float*)d_in[6];
    const float* b = (const float*)d_in[7];
    const float* w = (const float*)d_in[8];
    float* out = (float*)d_out;

    prep_kernel<<<256, 256>>>(A, R, r);
    kbuild_kernel<<<dim3(257, NK), 256>>>(R, r, a, b, w);
    ksum_kernel<<<NK, 256>>>();
    convp_kernel<<<dim3(NK, MAXCH, 64), dim3(32, 4)>>>();
    combine_kernel<<<256, 256>>>(m, s, h);
    sobelmu_kernel<<<256, 256>>>(A);
    gather_kernel<<<256, 256>>>(out);
}

// round 6
// speedup vs baseline: 1.4581x; 1.4581x over previous
#include <cuda_runtime.h>
#include <math.h>

#define NK 10
#define APW 544     // padded A row width (y+128 valid for y in [-128, 415])
#define CHUNK 32    // d rows per partial-conv block
#define MAXCH 8     // ceil((2*127+2)/32)

typedef unsigned long long u64;

// ---------------- scratch (static device globals; no allocation) ----------------
__device__ __align__(16) float  g_Apad[3][256][APW]; // planar A, y wrapped: [c][x][y+128]
__device__ __align__(16) float  g_Asum[256][256];
__device__ __align__(16) float  g_Kraw[NK][257][256]; // scalar kernels, row 256 = zero
__device__ __align__(16) u64    g_K2[NK][257][256];   // pair rows: (K[i][j], K[i+1][j]); row 256 = zero
__device__ double g_part[NK][256];
__device__ double g_ksum[NK];
__device__ int    g_rad[NK];
__device__ int    g_nch[NK];
__device__ __align__(16) float  g_pc[NK][MAXCH][256][256];  // partial conv sums (20MB)
__device__ __align__(16) float  g_U3[3][256][256];
__device__ __align__(16) float  g_mu[256*256*6];

__constant__ int c_C0[NK]  = {0,0,0,1,1,1,2,2,2,0};
__constant__ int c_grp[NK] = {0,0,0,1,1,1,2,2,2,0};

// ---------------- packed-f32x2 helpers ----------------
__device__ __forceinline__ u64 pkd(float v) {       // duplicate into both lanes
    u64 r; asm("mov.b64 %0, {%1, %1};" : "=l"(r) : "f"(v)); return r;
}
__device__ __forceinline__ void fma2(u64 &d, u64 a, u64 b) {
    asm("fma.rn.f32x2 %0, %1, %2, %0;" : "+l"(d) : "l"(a), "l"(b));
}
__device__ __forceinline__ float2 upk(u64 v) {
    float2 f; asm("mov.b64 {%0, %1}, %2;" : "=f"(f.x), "=f"(f.y) : "l"(v)); return f;
}

// ---------------- 1. prep: planar padded A, Asum, radii ----------------
__global__ void prep_kernel(const float* __restrict__ A,
                            const float* __restrict__ R,
                            const float* __restrict__ r) {
    int x = blockIdx.x, y = threadIdx.x;
    float a0 = A[(x*256+y)*3+0];
    float a1 = A[(x*256+y)*3+1];
    float a2 = A[(x*256+y)*3+2];
    g_Asum[x][y] = a0 + a1 + a2;
    for (int j = y; j < APW; j += 256) {
        int src = (j - 128) & 255;
        g_Apad[0][x][j] = A[(x*256+src)*3+0];
        g_Apad[1][x][j] = A[(x*256+src)*3+1];
        g_Apad[2][x][j] = A[(x*256+src)*3+2];
    }
    if (x == 0 && y < NK) {
        // sig = 0.5*(tanh(-(Dk-1)*5)+1) underflows to exactly 0 past Dk~2.58.
        float rc = 2.85f * (R[0] + 15.0f) * r[y];
        int rad = (int)rc + 1;
        rad = max(1, min(127, rad));
        g_rad[y] = rad;
        g_nch[y] = (2*rad + 2 + CHUNK - 1) / CHUNK;   // d in [-rad-1, rad]
    }
}

// ---------------- 2. build scalar kernels + per-row double sums ----------------
__global__ void kbuild_kernel(const float* __restrict__ R,
                              const float* __restrict__ r,
                              const float* __restrict__ a,
                              const float* __restrict__ b,
                              const float* __restrict__ w) {
    int i = blockIdx.x;   // dx + 128, or 256 = zero pad row
    int k = blockIdx.y;
    int j = threadIdx.x;  // dy + 128
    if (i == 256) {
        g_Kraw[k][256][j] = 0.0f;
        return;
    }
    float fdx = (float)(i - 128);
    float fdy = (float)(j - 128);
    float D  = sqrtf(fdx*fdx + fdy*fdy);
    float Dk = D / ((R[0] + 15.0f) * r[k]);
    float val = 0.0f;
    if (Dk < 2.9f) {   // sig exactly 0 (fp32 tanh saturation) past ~2.58
        float ker = 0.0f;
        #pragma unroll
        for (int t = 0; t < 3; t++) {
            float d = Dk - a[k*3+t];
            ker += b[k*3+t] * expf(-d*d / w[k*3+t]);
        }
        float sig = 0.5f * (tanhf(-(Dk - 1.0f) * 5.0f) + 1.0f);
        val = sig * ker;
    }
    g_Kraw[k][i][j] = val;

    __shared__ double sd[256];
    sd[j] = (double)val;
    __syncthreads();
    for (int s = 128; s > 0; s >>= 1) {
        if (j < s) sd[j] += sd[j + s];
        __syncthreads();
    }
    if (j == 0) g_part[k][i] = sd[0];
}

// ---------------- 2b. build x-pair packed kernel rows ----------------
__global__ void k2build_kernel() {
    int i = blockIdx.x;   // 0..256
    int k = blockIdx.y;
    int j = threadIdx.x;
    if (i == 256) { g_K2[k][256][j] = 0ull; return; }
    float lo = g_Kraw[k][i][j];
    float hi = g_Kraw[k][i+1][j];
    u64 v; asm("mov.b64 %0, {%1, %2};" : "=l"(v) : "f"(lo), "f"(hi));
    g_K2[k][i][j] = v;
}

// ---------------- 3. reduce row sums -> ksum (deterministic) ----------------
__global__ void ksum_kernel() {
    int k = blockIdx.x, j = threadIdx.x;
    __shared__ double sd[256];
    sd[j] = g_part[k][j];
    __syncthreads();
    for (int s = 128; s > 0; s >>= 1) {
        if (j < s) sd[j] += sd[j + s];
        __syncthreads();
    }
    if (j == 0) g_ksum[k] = sd[0];
}

// ---------------- 4. partial circular conv (x-paired f32x2, d-chunked) ----------------
// f32x2 lanes = outputs (x, x+1). For A row a = x - d:
//   out[x]   += K[d][u]   * A[a][y+u]
//   out[x+1] += K[d+1][u] * A[a][y+u]
// K pair (K[d],K[d+1]) preloaded in g_K2; A value broadcast to both lanes.
__global__ void __launch_bounds__(128) convp_kernel() {
    int k  = blockIdx.x;
    int ch = blockIdx.y;
    int rad = g_rad[k];
    if (ch >= g_nch[k]) return;

    int x  = (blockIdx.z * 2 + threadIdx.y) * 2;   // x pair base
    int c  = c_C0[k];
    int y0 = threadIdx.x << 2;                     // outputs y0..y0+3
    int yb = 128 + y0;

    int d0 = -rad - 1 + ch * CHUNK;
    int d1 = min(rad, d0 + CHUNK - 1);

    const float* __restrict__ Ap = &g_Apad[c][0][0];
    const u64*   __restrict__ K2 = &g_K2[k][0][0];

    float tL0=0.f,tL1=0.f,tL2=0.f,tL3=0.f;   // x
    float tH0=0.f,tH1=0.f,tH2=0.f,tH3=0.f;   // x+1

    for (int d = d0; d <= d1; ++d) {
        const float* __restrict__ Ar = Ap + ((x - d) & 255) * APW + yb;
        const u64*   __restrict__ Kr = K2 + (d + 128) * 256 + 128;

        int de = min(abs(d), abs(d+1));
        int rr = rad*rad - de*de;
        int radY = min(127, __float2int_rz(sqrtf((float)rr)) + 1);
        int us = -((radY + 3) & ~3);          // aligned start, covers [-radY, radY]

        u64 c0=0ull, c1=0ull, c2=0ull, c3=0ull;

        float4 cur = *(const float4*)(Ar + us);
        float4 nxt = *(const float4*)(Ar + us + 4);
        u64 D0 = pkd(cur.x), D1 = pkd(cur.y), D2 = pkd(cur.z);

        for (int u = us; u <= radY; u += 4) {
            ulonglong2 kA = *(const ulonglong2*)(Kr + u);      // taps u, u+1
            ulonglong2 kB = *(const ulonglong2*)(Kr + u + 2);  // taps u+2, u+3
            u64 D3 = pkd(cur.w);
            u64 D4 = pkd(nxt.x);
            u64 D5 = pkd(nxt.y);
            u64 D6 = pkd(nxt.z);

            fma2(c0, kA.x, D0); fma2(c1, kA.x, D1); fma2(c2, kA.x, D2); fma2(c3, kA.x, D3);
            fma2(c0, kA.y, D1); fma2(c1, kA.y, D2); fma2(c2, kA.y, D3); fma2(c3, kA.y, D4);
            fma2(c0, kB.x, D2); fma2(c1, kB.x, D3); fma2(c2, kB.x, D4); fma2(c3, kB.x, D5);
            fma2(c0, kB.y, D3); fma2(c1, kB.y, D4); fma2(c2, kB.y, D5); fma2(c3, kB.y, D6);

            D0 = D4; D1 = D5; D2 = D6;
            cur = nxt;
            nxt = *(const float4*)(Ar + u + 8);
        }

        float2 r0 = upk(c0), r1 = upk(c1), r2 = upk(c2), r3 = upk(c3);
        tL0 += r0.x; tL1 += r1.x; tL2 += r2.x; tL3 += r3.x;
        tH0 += r0.y; tH1 += r1.y; tH2 += r2.y; tH3 += r3.y;
    }

    *(float4*)&g_pc[k][ch][x][y0]     = make_float4(tL0, tL1, tL2, tL3);
    *(float4*)&g_pc[k][ch][x + 1][y0] = make_float4(tH0, tH1, tH2, tH3);
}

// ---------------- 5. combine partials + growth + channel-group sums ----------------
__global__ void combine_kernel(const float* __restrict__ m,
                               const float* __restrict__ s,
                               const float* __restrict__ h) {
    int x = blockIdx.x, y = threadIdx.x;
    float u0 = 0.f, u1 = 0.f, u2 = 0.f;
    #pragma unroll
    for (int k = 0; k < NK; k++) {
        int nch = g_nch[k];
        double acc = 0.0;
        for (int ch = 0; ch < nch; ch++)
            acc += (double)g_pc[k][ch][x][y];
        float U  = (float)(acc / g_ksum[k]);
        float gg = (U - m[k]) / s[k];
        float gr = (expf(-0.5f * gg * gg) * 2.0f - 1.0f) * h[k];
        int grp = c_grp[k];
        if (grp == 0) u0 += gr;
        else if (grp == 1) u1 += gr;
        else u2 += gr;
    }
    g_U3[0][x][y] = u0;
    g_U3[1][x][y] = u1;
    g_U3[2][x][y] = u2;
}

// ---------------- 6. sobel + flow F + mu ----------------
__device__ __forceinline__ float padv(const float* p, int xx, int yy) {
    return (xx >= 0 && xx < 256 && yy >= 0 && yy < 256) ? p[xx*256 + yy] : 0.0f;
}

__global__ void sobelmu_kernel(const float* __restrict__ A) {
    int x = blockIdx.x, y = threadIdx.x;
    const float* As = &g_Asum[0][0];
    float nA0 = (padv(As,x-1,y-1) + 2.0f*padv(As,x-1,y) + padv(As,x-1,y+1))
              - (padv(As,x+1,y-1) + 2.0f*padv(As,x+1,y) + padv(As,x+1,y+1));
    float nA1 = (padv(As,x-1,y-1) + 2.0f*padv(As,x,y-1) + padv(As,x+1,y-1))
              - (padv(As,x-1,y+1) + 2.0f*padv(As,x,y+1) + padv(As,x+1,y+1));

    float px = (float)x + 0.5f;
    float py = (float)y + 0.5f;
    #pragma unroll
    for (int c = 0; c < 3; c++) {
        const float* Uc = &g_U3[c][0][0];
        float nU0 = (padv(Uc,x-1,y-1) + 2.0f*padv(Uc,x-1,y) + padv(Uc,x-1,y+1))
                  - (padv(Uc,x+1,y-1) + 2.0f*padv(Uc,x+1,y) + padv(Uc,x+1,y+1));
        float nU1 = (padv(Uc,x-1,y-1) + 2.0f*padv(Uc,x,y-1) + padv(Uc,x+1,y-1))
                  - (padv(Uc,x-1,y+1) + 2.0f*padv(Uc,x,y+1) + padv(Uc,x+1,y+1));
        float Ac = A[(x*256+y)*3 + c];
        float al = Ac * (1.0f/3.0f);
        al = al * al;
        al = fminf(al, 1.0f);
        float F0 = nU0 * (1.0f - al) - nA0 * al;
        float F1 = nU1 * (1.0f - al) - nA1 * al;
        float d0 = fminf(fmaxf(0.2f * F0, -4.35f), 4.35f);
        float d1 = fminf(fmaxf(0.2f * F1, -4.35f), 4.35f);
        float mux = fminf(fmaxf(px + d0, 0.65f), 255.35f);
        float muy = fminf(fmaxf(py + d1, 0.65f), 255.35f);
        g_mu[(x*256+y)*6 + c*2 + 0] = mux;
        g_mu[(x*256+y)*6 + c*2 + 1] = muy;
    }
}

// ---------------- 7. reintegration tracking (gather form) ----------------
__global__ void gather_kernel(float* __restrict__ out) {
    int x = blockIdx.x, y = threadIdx.x;
    float px = (float)x + 0.5f;
    float py = (float)y + 0.5f;
    float acc0 = 0.0f, acc1 = 0.0f, acc2 = 0.0f;
    const float inv = 1.0f / 1.69f;   // 1/(4*sigma^2)

    #pragma unroll
    for (int dx = -5; dx <= 5; ++dx) {
        int i = (x - dx) & 255;
        #pragma unroll
        for (int dy = -5; dy <= 5; ++dy) {
            int j = (y - dy) & 255;
            const float* mu = g_mu + (i*256 + j)*6;
            #pragma unroll
            for (int c = 0; c < 3; c++) {
                float ax = 1.15f - fabsf(px - mu[2*c + 0]);
                float ay = 1.15f - fabsf(py - mu[2*c + 1]);
                ax = fminf(fmaxf(ax, 0.0f), 1.0f);
                ay = fminf(fmaxf(ay, 0.0f), 1.0f);
                float area = ax * ay * inv;
                float av = g_Apad[c][i][j + 128];
                if (c == 0) acc0 = fmaf(av, area, acc0);
                else if (c == 1) acc1 = fmaf(av, area, acc1);
                else acc2 = fmaf(av, area, acc2);
            }
        }
    }
    out[(x*256+y)*3 + 0] = acc0;
    out[(x*256+y)*3 + 1] = acc1;
    out[(x*256+y)*3 + 2] = acc2;
}

// ---------------- launch ----------------
extern "C" void kernel_launch(void* const* d_in, const int* in_sizes, int n_in,
                              void* d_out, int out_size) {
    const float* A = (const float*)d_in[0];
    const float* R = (const float*)d_in[1];
    const float* r = (const float*)d_in[2];
    const float* m = (const float*)d_in[3];
    const float* s = (const float*)d_in[4];
    const float* h = (const float*)d_in[5];
    const float* a = (const float*)d_in[6];
    const float* b = (const float*)d_in[7];
    const float* w = (const float*)d_in[8];
    float* out = (float*)d_out;

    prep_kernel<<<256, 256>>>(A, R, r);
    kbuild_kernel<<<dim3(257, NK), 256>>>(R, r, a, b, w);
    k2build_kernel<<<dim3(257, NK), 256>>>();
    ksum_kernel<<<NK, 256>>>();
    convp_kernel<<<dim3(NK, MAXCH, 64), dim3(64, 2)>>>();
    combine_kernel<<<256, 256>>>(m, s, h);
    sobelmu_kernel<<<256, 256>>>(A);
    gather_kernel<<<256, 256>>>(out);
}

// round 7
// speedup vs baseline: 1.5904x; 1.0907x over previous
#include <cuda_runtime.h>
#include <math.h>

#define NK 10
#define APW 544     // padded A row width (y+128 valid for y in [-128, 415])
#define CHUNK 32    // d rows per partial-conv block
#define MAXCH 8     // ceil((2*127+2)/32)

typedef unsigned long long u64;

// ---------------- scratch (static device globals; no allocation) ----------------
__device__ __align__(16) float  g_Apad[3][256][APW]; // planar A, y wrapped: [c][x][y+128]
__device__ __align__(16) float  g_Asum[256][256];
__device__ __align__(16) u64    g_K2[NK][257][256];  // pair rows: (K[i][j], K[i+1][j]); row 256 = zero
__device__ double g_part[NK][256];
__device__ double g_ksum[NK];
__device__ int    g_rad[NK];
__device__ int    g_nch[NK];
__device__ __align__(16) float  g_pc[NK][MAXCH][256][256];  // partial conv sums (20MB)
__device__ __align__(16) float  g_U3[3][256][256];
__device__ __align__(16) float  g_mu[256*256*6];

__constant__ int c_C0[NK]  = {0,0,0,1,1,1,2,2,2,0};
__constant__ int c_grp[NK] = {0,0,0,1,1,1,2,2,2,0};

// ---------------- packed-f32x2 helpers ----------------
__device__ __forceinline__ u64 pkd(float v) {       // duplicate into both lanes
    u64 r; asm("mov.b64 %0, {%1, %1};" : "=l"(r) : "f"(v)); return r;
}
__device__ __forceinline__ u64 pk2(float lo, float hi) {
    u64 r; asm("mov.b64 %0, {%1, %2};" : "=l"(r) : "f"(lo), "f"(hi)); return r;
}
__device__ __forceinline__ void fma2(u64 &d, u64 a, u64 b) {
    asm("fma.rn.f32x2 %0, %1, %2, %0;" : "+l"(d) : "l"(a), "l"(b));
}
__device__ __forceinline__ float2 upk(u64 v) {
    float2 f; asm("mov.b64 {%0, %1}, %2;" : "=f"(f.x), "=f"(f.y) : "l"(v)); return f;
}

// ---------------- 1. prep: planar padded A, Asum, radii ----------------
__global__ void prep_kernel(const float* __restrict__ A,
                            const float* __restrict__ R,
                            const float* __restrict__ r) {
    int x = blockIdx.x, y = threadIdx.x;
    float a0 = A[(x*256+y)*3+0];
    float a1 = A[(x*256+y)*3+1];
    float a2 = A[(x*256+y)*3+2];
    g_Asum[x][y] = a0 + a1 + a2;
    for (int j = y; j < APW; j += 256) {
        int src = (j - 128) & 255;
        g_Apad[0][x][j] = A[(x*256+src)*3+0];
        g_Apad[1][x][j] = A[(x*256+src)*3+1];
        g_Apad[2][x][j] = A[(x*256+src)*3+2];
    }
    if (x == 0 && y < NK) {
        // sig at Dk=2.70 is ~2e-8; truncation error stays far inside tolerance.
        float rc = 2.70f * (R[0] + 15.0f) * r[y];
        int rad = (int)rc + 1;
        rad = max(1, min(127, rad));
        g_rad[y] = rad;
        g_nch[y] = (2*rad + 2 + CHUNK - 1) / CHUNK;   // d in [-rad-1, rad]
    }
}

// ---------------- 2. build packed pair kernels + per-row double sums ----------------
__device__ __forceinline__ float kval(float fdx, float fdy, float S,
                                      const float* a, const float* b, const float* w, int k) {
    float D  = sqrtf(fdx*fdx + fdy*fdy);
    float Dk = D / S;
    float val = 0.0f;
    if (Dk < 2.9f) {   // sig exactly 0 (fp32 tanh saturation) past ~2.74
        float ker = 0.0f;
        #pragma unroll
        for (int t = 0; t < 3; t++) {
            float d = Dk - a[k*3+t];
            ker += b[k*3+t] * expf(-d*d / w[k*3+t]);
        }
        float sig = 0.5f * (tanhf(-(Dk - 1.0f) * 5.0f) + 1.0f);
        val = sig * ker;
    }
    return val;
}

__global__ void kbuild_kernel(const float* __restrict__ R,
                              const float* __restrict__ r,
                              const float* __restrict__ a,
                              const float* __restrict__ b,
                              const float* __restrict__ w) {
    int i = blockIdx.x;   // 0..256 (row 256 = zero pad)
    int k = blockIdx.y;
    int j = threadIdx.x;  // dy + 128
    if (i == 256) {
        g_K2[k][256][j] = 0ull;
        return;
    }
    float S = (R[0] + 15.0f) * r[k];
    float fdy = (float)(j - 128);
    float v0 = kval((float)(i - 128), fdy, S, a, b, w, k);
    float v1 = kval((float)(i - 127), fdy, S, a, b, w, k);  // i+1==256 -> dx=128 -> Dk>2.9 -> 0
    g_K2[k][i][j] = pk2(v0, v1);

    __shared__ double sd[256];
    sd[j] = (double)v0;
    __syncthreads();
    for (int s = 128; s > 0; s >>= 1) {
        if (j < s) sd[j] += sd[j + s];
        __syncthreads();
    }
    if (j == 0) g_part[k][i] = sd[0];
}

// ---------------- 3. reduce row sums -> ksum (deterministic) ----------------
__global__ void ksum_kernel() {
    int k = blockIdx.x, j = threadIdx.x;
    __shared__ double sd[256];
    sd[j] = g_part[k][j];
    __syncthreads();
    for (int s = 128; s > 0; s >>= 1) {
        if (j < s) sd[j] += sd[j + s];
        __syncthreads();
    }
    if (j == 0) g_ksum[k] = sd[0];
}

// ---------------- 4. partial circular conv (x-paired f32x2, d-chunked) ----------------
// f32x2 lanes = outputs (x, x+1). For A row a = x - d:
//   out[x]   += K[d][u]   * A[a][y+u]
//   out[x+1] += K[d+1][u] * A[a][y+u]
__global__ void __launch_bounds__(128) convp_kernel() {
    int k  = blockIdx.x;
    int ch = blockIdx.y;
    int rad = g_rad[k];
    if (ch >= g_nch[k]) return;

    int x  = (blockIdx.z * 2 + threadIdx.y) * 2;   // x pair base
    int c  = c_C0[k];
    int y0 = threadIdx.x << 2;                     // outputs y0..y0+3
    int yb = 128 + y0;

    int d0 = -rad - 1 + ch * CHUNK;
    int d1 = min(rad, d0 + CHUNK - 1);

    const float* __restrict__ Ap = &g_Apad[c][0][0];
    const u64*   __restrict__ K2 = &g_K2[k][0][0];

    float tL0=0.f,tL1=0.f,tL2=0.f,tL3=0.f;   // x
    float tH0=0.f,tH1=0.f,tH2=0.f,tH3=0.f;   // x+1

    for (int d = d0; d <= d1; ++d) {
        const float* __restrict__ Ar = Ap + ((x - d) & 255) * APW + yb;
        const u64*   __restrict__ Kr = K2 + (d + 128) * 256 + 128;

        int de = min(abs(d), abs(d+1));
        int rr = rad*rad - de*de;
        int radY = min(127, __float2int_rz(sqrtf((float)rr)) + 1);
        int us = -((radY + 3) & ~3);          // aligned start, covers [-radY, radY]

        u64 c0=0ull, c1=0ull, c2=0ull, c3=0ull;

        float4 cur = *(const float4*)(Ar + us);
        float4 nxt = *(const float4*)(Ar + us + 4);
        u64 D0 = pkd(cur.x), D1 = pkd(cur.y), D2 = pkd(cur.z);

        for (int u = us; u <= radY; u += 4) {
            ulonglong2 kA = *(const ulonglong2*)(Kr + u);      // taps u, u+1
            ulonglong2 kB = *(const ulonglong2*)(Kr + u + 2);  // taps u+2, u+3
            u64 D3 = pkd(cur.w);
            u64 D4 = pkd(nxt.x);
            u64 D5 = pkd(nxt.y);
            u64 D6 = pkd(nxt.z);

            fma2(c0, kA.x, D0); fma2(c1, kA.x, D1); fma2(c2, kA.x, D2); fma2(c3, kA.x, D3);
            fma2(c0, kA.y, D1); fma2(c1, kA.y, D2); fma2(c2, kA.y, D3); fma2(c3, kA.y, D4);
            fma2(c0, kB.x, D2); fma2(c1, kB.x, D3); fma2(c2, kB.x, D4); fma2(c3, kB.x, D5);
            fma2(c0, kB.y, D3); fma2(c1, kB.y, D4); fma2(c2, kB.y, D5); fma2(c3, kB.y, D6);

            D0 = D4; D1 = D5; D2 = D6;
            cur = nxt;
            nxt = *(const float4*)(Ar + u + 8);
        }

        float2 r0 = upk(c0), r1 = upk(c1), r2 = upk(c2), r3 = upk(c3);
        tL0 += r0.x; tL1 += r1.x; tL2 += r2.x; tL3 += r3.x;
        tH0 += r0.y; tH1 += r1.y; tH2 += r2.y; tH3 += r3.y;
    }

    *(float4*)&g_pc[k][ch][x][y0]     = make_float4(tL0, tL1, tL2, tL3);
    *(float4*)&g_pc[k][ch][x + 1][y0] = make_float4(tH0, tH1, tH2, tH3);
}

// ---------------- 5. combine partials + growth + channel-group sums ----------------
__global__ void combine_kernel(const float* __restrict__ m,
                               const float* __restrict__ s,
                               const float* __restrict__ h) {
    int x = blockIdx.x, y = threadIdx.x;
    float u0 = 0.f, u1 = 0.f, u2 = 0.f;
    #pragma unroll
    for (int k = 0; k < NK; k++) {
        int nch = g_nch[k];
        double acc = 0.0;
        for (int ch = 0; ch < nch; ch++)
            acc += (double)g_pc[k][ch][x][y];
        float U  = (float)(acc / g_ksum[k]);
        float gg = (U - m[k]) / s[k];
        float gr = (expf(-0.5f * gg * gg) * 2.0f - 1.0f) * h[k];
        int grp = c_grp[k];
        if (grp == 0) u0 += gr;
        else if (grp == 1) u1 += gr;
        else u2 += gr;
    }
    g_U3[0][x][y] = u0;
    g_U3[1][x][y] = u1;
    g_U3[2][x][y] = u2;
}

// ---------------- 6. sobel + flow F + mu ----------------
__device__ __forceinline__ float padv(const float* p, int xx, int yy) {
    return (xx >= 0 && xx < 256 && yy >= 0 && yy < 256) ? p[xx*256 + yy] : 0.0f;
}

__global__ void sobelmu_kernel(const float* __restrict__ A) {
    int x = blockIdx.x, y = threadIdx.x;
    const float* As = &g_Asum[0][0];
    float nA0 = (padv(As,x-1,y-1) + 2.0f*padv(As,x-1,y) + padv(As,x-1,y+1))
              - (padv(As,x+1,y-1) + 2.0f*padv(As,x+1,y) + padv(As,x+1,y+1));
    float nA1 = (padv(As,x-1,y-1) + 2.0f*padv(As,x,y-1) + padv(As,x+1,y-1))
              - (padv(As,x-1,y+1) + 2.0f*padv(As,x,y+1) + padv(As,x+1,y+1));

    float px = (float)x + 0.5f;
    float py = (float)y + 0.5f;
    #pragma unroll
    for (int c = 0; c < 3; c++) {
        const float* Uc = &g_U3[c][0][0];
        float nU0 = (padv(Uc,x-1,y-1) + 2.0f*padv(Uc,x-1,y) + padv(Uc,x-1,y+1))
                  - (padv(Uc,x+1,y-1) + 2.0f*padv(Uc,x+1,y) + padv(Uc,x+1,y+1));
        float nU1 = (padv(Uc,x-1,y-1) + 2.0f*padv(Uc,x,y-1) + padv(Uc,x+1,y-1))
                  - (padv(Uc,x-1,y+1) + 2.0f*padv(Uc,x,y+1) + padv(Uc,x+1,y+1));
        float Ac = A[(x*256+y)*3 + c];
        float al = Ac * (1.0f/3.0f);
        al = al * al;
        al = fminf(al, 1.0f);
        float F0 = nU0 * (1.0f - al) - nA0 * al;
        float F1 = nU1 * (1.0f - al) - nA1 * al;
        float d0 = fminf(fmaxf(0.2f * F0, -4.35f), 4.35f);
        float d1 = fminf(fmaxf(0.2f * F1, -4.35f), 4.35f);
        float mux = fminf(fmaxf(px + d0, 0.65f), 255.35f);
        float muy = fminf(fmaxf(py + d1, 0.65f), 255.35f);
        g_mu[(x*256+y)*6 + c*2 + 0] = mux;
        g_mu[(x*256+y)*6 + c*2 + 1] = muy;
    }
}

// ---------------- 7. reintegration tracking (smem-tiled gather) ----------------
__global__ void __launch_bounds__(256) gather_kernel(float* __restrict__ out) {
    __shared__ float s_mu[26*26*6];
    __shared__ float s_a[26*26*3];
    int tid = threadIdx.x;
    int tx = tid & 15;    // y within tile
    int ty = tid >> 4;    // x within tile
    int X0 = blockIdx.x * 16, Y0 = blockIdx.y * 16;

    for (int idx = tid; idx < 26*26; idx += 256) {
        int ii = idx / 26, jj = idx - ii*26;
        int gi = (X0 - 5 + ii) & 255;
        int gj = (Y0 - 5 + jj) & 255;
        const float2* mu = (const float2*)(g_mu + (gi*256 + gj)*6);
        float2* d = (float2*)(s_mu + idx*6);
        d[0] = mu[0]; d[1] = mu[1]; d[2] = mu[2];
        s_a[idx*3+0] = g_Apad[0][gi][gj+128];
        s_a[idx*3+1] = g_Apad[1][gi][gj+128];
        s_a[idx*3+2] = g_Apad[2][gi][gj+128];
    }
    __syncthreads();

    int x = X0 + ty, y = Y0 + tx;
    float px = (float)x + 0.5f;
    float py = (float)y + 0.5f;
    float acc0 = 0.0f, acc1 = 0.0f, acc2 = 0.0f;
    const float inv = 1.0f / 1.69f;   // 1/(4*sigma^2)

    #pragma unroll
    for (int dx = -5; dx <= 5; ++dx) {
        int si = ty + 5 - dx;
        #pragma unroll
        for (int dy = -5; dy <= 5; ++dy) {
            int sj = tx + 5 - dy;
            int base = si*26 + sj;
            const float* mu = s_mu + base*6;
            const float* av = s_a + base*3;
            #pragma unroll
            for (int c = 0; c < 3; c++) {
                float ax = 1.15f - fabsf(px - mu[2*c + 0]);
                float ay = 1.15f - fabsf(py - mu[2*c + 1]);
                ax = fminf(fmaxf(ax, 0.0f), 1.0f);
                ay = fminf(fmaxf(ay, 0.0f), 1.0f);
                float area = ax * ay * inv;
                if (c == 0) acc0 = fmaf(av[0], area, acc0);
                else if (c == 1) acc1 = fmaf(av[1], area, acc1);
                else acc2 = fmaf(av[2], area, acc2);
            }
        }
    }
    out[(x*256+y)*3 + 0] = acc0;
    out[(x*256+y)*3 + 1] = acc1;
    out[(x*256+y)*3 + 2] = acc2;
}

// ---------------- launch ----------------
extern "C" void kernel_launch(void* const* d_in, const int* in_sizes, int n_in,
                              void* d_out, int out_size) {
    const float* A = (const float*)d_in[0];
    const float* R = (const float*)d_in[1];
    const float* r = (const float*)d_in[2];
    const float* m = (const float*)d_in[3];
    const float* s = (const float*)d_in[4];
    const float* h = (const float*)d_in[5];
    const float* a = (const float*)d_in[6];
    const float* b = (const float*)d_in[7];
    const float* w = (const float*)d_in[8];
    float* out = (float*)d_out;

    prep_kernel<<<256, 256>>>(A, R, r);
    kbuild_kernel<<<dim3(257, NK), 256>>>(R, r, a, b, w);
    ksum_kernel<<<NK, 256>>>();
    convp_kernel<<<dim3(NK, MAXCH, 64), dim3(64, 2)>>>();
    combine_kernel<<<256, 256>>>(m, s, h);
    sobelmu_kernel<<<256, 256>>>(A);
    gather_kernel<<<dim3(16, 16), 256>>>(out);
}

// round 8
// speedup vs baseline: 1.7063x; 1.0728x over previous
#include <cuda_runtime.h>
#include <math.h>

#define NK 10
#define APW 544     // padded A row width (y+128 valid for y in [-128, 415])
#define CHUNK 16    // d' rows per partial-conv block
#define MAXCH 16
#define KOFF 132    // K2 row offset: row i <-> K[d = i-132]
#define KROWS 264

typedef unsigned long long u64;

// ---------------- scratch (static device globals; no allocation) ----------------
__device__ __align__(16) float  g_Apad[3][256][APW]; // planar A, y wrapped: [c][x][y+128]
__device__ __align__(16) float  g_Asum[256][256];
__device__ __align__(16) u64    g_K2[NK][KROWS][256]; // pair rows: (K[i-KOFF][j], K[i-KOFF+1][j])
__device__ double g_part[NK][KROWS];
__device__ double g_ksum[NK];
__device__ int    g_rad[NK];
__device__ int    g_nch[NK];
__device__ __align__(16) float  g_pc[NK][MAXCH][256][256];  // partial conv sums (42MB)
__device__ __align__(16) float  g_U3[3][256][256];
__device__ __align__(16) float  g_mu[256*256*6];

__constant__ int c_C0[NK]  = {0,0,0,1,1,1,2,2,2,0};
__constant__ int c_grp[NK] = {0,0,0,1,1,1,2,2,2,0};

// ---------------- packed-f32x2 helpers ----------------
__device__ __forceinline__ u64 pkd(float v) {       // duplicate into both lanes
    u64 r; asm("mov.b64 %0, {%1, %1};" : "=l"(r) : "f"(v)); return r;
}
__device__ __forceinline__ u64 pk2(float lo, float hi) {
    u64 r; asm("mov.b64 %0, {%1, %2};" : "=l"(r) : "f"(lo), "f"(hi)); return r;
}
__device__ __forceinline__ void fma2(u64 &d, u64 a, u64 b) {
    asm("fma.rn.f32x2 %0, %1, %2, %0;" : "+l"(d) : "l"(a), "l"(b));
}
__device__ __forceinline__ float2 upk(u64 v) {
    float2 f; asm("mov.b64 {%0, %1}, %2;" : "=f"(f.x), "=f"(f.y) : "l"(v)); return f;
}

// ---------------- 1. prep: planar padded A, Asum, radii ----------------
__global__ void prep_kernel(const float* __restrict__ A,
                            const float* __restrict__ R,
                            const float* __restrict__ r) {
    int x = blockIdx.x, y = threadIdx.x;
    float a0 = A[(x*256+y)*3+0];
    float a1 = A[(x*256+y)*3+1];
    float a2 = A[(x*256+y)*3+2];
    g_Asum[x][y] = a0 + a1 + a2;
    for (int j = y; j < APW; j += 256) {
        int src = (j - 128) & 255;
        g_Apad[0][x][j] = A[(x*256+src)*3+0];
        g_Apad[1][x][j] = A[(x*256+src)*3+1];
        g_Apad[2][x][j] = A[(x*256+src)*3+2];
    }
    if (x == 0 && y < NK) {
        // sig at Dk=2.70 is ~2e-8; truncation error far inside tolerance.
        float rc = 2.70f * (R[0] + 15.0f) * r[y];
        int rad = (int)rc + 1;
        rad = max(1, min(127, rad));
        g_rad[y] = rad;
        g_nch[y] = (2*rad + 4 + CHUNK - 1) / CHUNK;   // d' in [-rad-3, rad]
    }
}

// ---------------- 2. build packed pair kernels + per-row double sums ----------------
__device__ __forceinline__ float kval(float fdx, float fdy, float S,
                                      const float* a, const float* b, const float* w, int k) {
    float D  = sqrtf(fdx*fdx + fdy*fdy);
    float Dk = D / S;
    float val = 0.0f;
    if (Dk < 2.9f) {   // sig exactly 0 (fp32 tanh saturation) past ~2.74
        float ker = 0.0f;
        #pragma unroll
        for (int t = 0; t < 3; t++) {
            float d = Dk - a[k*3+t];
            ker += b[k*3+t] * expf(-d*d / w[k*3+t]);
        }
        float sig = 0.5f * (tanhf(-(Dk - 1.0f) * 5.0f) + 1.0f);
        val = sig * ker;
    }
    return val;
}

__global__ void kbuild_kernel(const float* __restrict__ R,
                              const float* __restrict__ r,
                              const float* __restrict__ a,
                              const float* __restrict__ b,
                              const float* __restrict__ w) {
    int i = blockIdx.x;   // 0..KROWS-1, d = i - KOFF
    int k = blockIdx.y;
    int j = threadIdx.x;  // dy + 128
    float S = (R[0] + 15.0f) * r[k];
    float fdy = (float)(j - 128);
    float fdx = (float)(i - KOFF);
    float v0 = kval(fdx,        fdy, S, a, b, w, k);
    float v1 = kval(fdx + 1.0f, fdy, S, a, b, w, k);
    g_K2[k][i][j] = pk2(v0, v1);

    __shared__ double sd[256];
    sd[j] = (double)v0;
    __syncthreads();
    for (int s = 128; s > 0; s >>= 1) {
        if (j < s) sd[j] += sd[j + s];
        __syncthreads();
    }
    if (j == 0) g_part[k][i] = sd[0];
}

// ---------------- 3. reduce row sums -> ksum (deterministic) ----------------
__global__ void ksum_kernel() {
    int k = blockIdx.x, j = threadIdx.x;
    __shared__ double sd[256];
    double v = g_part[k][j];
    if (j < KROWS - 256) v += g_part[k][256 + j];
    sd[j] = v;
    __syncthreads();
    for (int s = 128; s > 0; s >>= 1) {
        if (j < s) sd[j] += sd[j + s];
        __syncthreads();
    }
    if (j == 0) g_ksum[k] = sd[0];
}

// ---------------- 4. partial circular conv (x-quad f32x2, d'-chunked) ----------------
// Thread owns outputs x..x+3 at y0..y0+3. For A row a = x - d':
//   (x  ,x+1) use K2[d'+KOFF]   = (K[d'],  K[d'+1])
//   (x+2,x+3) use K2[d'+KOFF+2] = (K[d'+2],K[d'+3])
// One A sliding window feeds all 8 f32x2 accumulators.
__global__ void __launch_bounds__(128) convp_kernel() {
    int k  = blockIdx.x;
    int ch = blockIdx.y;
    int rad = g_rad[k];
    if (ch >= g_nch[k]) return;

    int x  = (blockIdx.z * 2 + threadIdx.y) * 4;   // x quad base
    int c  = c_C0[k];
    int y0 = threadIdx.x << 2;                     // outputs y0..y0+3
    int yb = 128 + y0;

    int d0 = -rad - 3 + ch * CHUNK;
    int d1 = min(rad, d0 + CHUNK - 1);

    const float* __restrict__ Ap = &g_Apad[c][0][0];
    const u64*   __restrict__ K2 = &g_K2[k][0][0];

    u64 c0=0ull, c1=0ull, c2=0ull, c3=0ull;   // (x, x+1)   cols y0..y0+3
    u64 e0=0ull, e1=0ull, e2=0ull, e3=0ull;   // (x+2, x+3) cols y0..y0+3

    for (int d = d0; d <= d1; ++d) {
        const float* __restrict__ Ar  = Ap + ((x - d) & 255) * APW + yb;
        const u64*   __restrict__ Kr1 = K2 + (d + KOFF) * 256 + 128;
        const u64*   __restrict__ Kr2 = Kr1 + 512;

        int hi = d + 3;
        int de = (d > 0) ? d : ((hi < 0) ? -hi : 0);
        int rr = rad*rad - de*de;
        int radY = min(127, __float2int_rz(sqrtf((float)rr)) + 1);
        int us = -((radY + 3) & ~3);          // aligned start, covers [-radY, radY]

        float4 cur = *(const float4*)(Ar + us);
        float4 nxt = *(const float4*)(Ar + us + 4);
        u64 D0 = pkd(cur.x), D1 = pkd(cur.y), D2 = pkd(cur.z);

        for (int u = us; u <= radY; u += 4) {
            ulonglong2 kA = *(const ulonglong2*)(Kr1 + u);      // (K[d],K[d+1]) taps u,u+1
            ulonglong2 kB = *(const ulonglong2*)(Kr1 + u + 2);  // taps u+2,u+3
            ulonglong2 kC = *(const ulonglong2*)(Kr2 + u);      // (K[d+2],K[d+3]) taps u,u+1
            ulonglong2 kD = *(const ulonglong2*)(Kr2 + u + 2);
            u64 D3 = pkd(cur.w);
            u64 D4 = pkd(nxt.x);
            u64 D5 = pkd(nxt.y);
            u64 D6 = pkd(nxt.z);

            fma2(c0, kA.x, D0); fma2(c1, kA.x, D1); fma2(c2, kA.x, D2); fma2(c3, kA.x, D3);
            fma2(e0, kC.x, D0); fma2(e1, kC.x, D1); fma2(e2, kC.x, D2); fma2(e3, kC.x, D3);
            fma2(c0, kA.y, D1); fma2(c1, kA.y, D2); fma2(c2, kA.y, D3); fma2(c3, kA.y, D4);
            fma2(e0, kC.y, D1); fma2(e1, kC.y, D2); fma2(e2, kC.y, D3); fma2(e3, kC.y, D4);
            fma2(c0, kB.x, D2); fma2(c1, kB.x, D3); fma2(c2, kB.x, D4); fma2(c3, kB.x, D5);
            fma2(e0, kD.x, D2); fma2(e1, kD.x, D3); fma2(e2, kD.x, D4); fma2(e3, kD.x, D5);
            fma2(c0, kB.y, D3); fma2(c1, kB.y, D4); fma2(c2, kB.y, D5); fma2(c3, kB.y, D6);
            fma2(e0, kD.y, D3); fma2(e1, kD.y, D4); fma2(e2, kD.y, D5); fma2(e3, kD.y, D6);

            D0 = D4; D1 = D5; D2 = D6;
            cur = nxt;
            nxt = *(const float4*)(Ar + u + 8);
        }
    }

    float2 r0 = upk(c0), r1 = upk(c1), r2 = upk(c2), r3 = upk(c3);
    float2 s0 = upk(e0), s1 = upk(e1), s2 = upk(e2), s3 = upk(e3);
    *(float4*)&g_pc[k][ch][x    ][y0] = make_float4(r0.x, r1.x, r2.x, r3.x);
    *(float4*)&g_pc[k][ch][x + 1][y0] = make_float4(r0.y, r1.y, r2.y, r3.y);
    *(float4*)&g_pc[k][ch][x + 2][y0] = make_float4(s0.x, s1.x, s2.x, s3.x);
    *(float4*)&g_pc[k][ch][x + 3][y0] = make_float4(s0.y, s1.y, s2.y, s3.y);
}

// ---------------- 5. combine partials + growth + channel-group sums ----------------
__global__ void combine_kernel(const float* __restrict__ m,
                               const float* __restrict__ s,
                               const float* __restrict__ h) {
    int x = blockIdx.x, y = threadIdx.x;
    float u0 = 0.f, u1 = 0.f, u2 = 0.f;
    #pragma unroll
    for (int k = 0; k < NK; k++) {
        int nch = g_nch[k];
        double acc = 0.0;
        for (int ch = 0; ch < nch; ch++)
            acc += (double)g_pc[k][ch][x][y];
        float U  = (float)(acc / g_ksum[k]);
        float gg = (U - m[k]) / s[k];
        float gr = (expf(-0.5f * gg * gg) * 2.0f - 1.0f) * h[k];
        int grp = c_grp[k];
        if (grp == 0) u0 += gr;
        else if (grp == 1) u1 += gr;
        else u2 += gr;
    }
    g_U3[0][x][y] = u0;
    g_U3[1][x][y] = u1;
    g_U3[2][x][y] = u2;
}

// ---------------- 6. sobel + flow F + mu ----------------
__device__ __forceinline__ float padv(const float* p, int xx, int yy) {
    return (xx >= 0 && xx < 256 && yy >= 0 && yy < 256) ? p[xx*256 + yy] : 0.0f;
}

__global__ void sobelmu_kernel(const float* __restrict__ A) {
    int x = blockIdx.x, y = threadIdx.x;
    const float* As = &g_Asum[0][0];
    float nA0 = (padv(As,x-1,y-1) + 2.0f*padv(As,x-1,y) + padv(As,x-1,y+1))
              - (padv(As,x+1,y-1) + 2.0f*padv(As,x+1,y) + padv(As,x+1,y+1));
    float nA1 = (padv(As,x-1,y-1) + 2.0f*padv(As,x,y-1) + padv(As,x+1,y-1))
              - (padv(As,x-1,y+1) + 2.0f*padv(As,x,y+1) + padv(As,x+1,y+1));

    float px = (float)x + 0.5f;
    float py = (float)y + 0.5f;
    #pragma unroll
    for (int c = 0; c < 3; c++) {
        const float* Uc = &g_U3[c][0][0];
        float nU0 = (padv(Uc,x-1,y-1) + 2.0f*padv(Uc,x-1,y) + padv(Uc,x-1,y+1))
                  - (padv(Uc,x+1,y-1) + 2.0f*padv(Uc,x+1,y) + padv(Uc,x+1,y+1));
        float nU1 = (padv(Uc,x-1,y-1) + 2.0f*padv(Uc,x,y-1) + padv(Uc,x+1,y-1))
                  - (padv(Uc,x-1,y+1) + 2.0f*padv(Uc,x,y+1) + padv(Uc,x+1,y+1));
        float Ac = A[(x*256+y)*3 + c];
        float al = Ac * (1.0f/3.0f);
        al = al * al;
        al = fminf(al, 1.0f);
        float F0 = nU0 * (1.0f - al) - nA0 * al;
        float F1 = nU1 * (1.0f - al) - nA1 * al;
        float d0 = fminf(fmaxf(0.2f * F0, -4.35f), 4.35f);
        float d1 = fminf(fmaxf(0.2f * F1, -4.35f), 4.35f);
        float mux = fminf(fmaxf(px + d0, 0.65f), 255.35f);
        float muy = fminf(fmaxf(py + d1, 0.65f), 255.35f);
        g_mu[(x*256+y)*6 + c*2 + 0] = mux;
        g_mu[(x*256+y)*6 + c*2 + 1] = muy;
    }
}

// ---------------- 7. reintegration tracking (smem-tiled gather) ----------------
__global__ void __launch_bounds__(256) gather_kernel(float* __restrict__ out) {
    __shared__ float s_mu[26*26*6];
    __shared__ float s_a[26*26*3];
    int tid = threadIdx.x;
    int tx = tid & 15;    // y within tile
    int ty = tid >> 4;    // x within tile
    int X0 = blockIdx.x * 16, Y0 = blockIdx.y * 16;

    for (int idx = tid; idx < 26*26; idx += 256) {
        int ii = idx / 26, jj = idx - ii*26;
        int gi = (X0 - 5 + ii) & 255;
        int gj = (Y0 - 5 + jj) & 255;
        const float2* mu = (const float2*)(g_mu + (gi*256 + gj)*6);
        float2* d = (float2*)(s_mu + idx*6);
        d[0] = mu[0]; d[1] = mu[1]; d[2] = mu[2];
        s_a[idx*3+0] = g_Apad[0][gi][gj+128];
        s_a[idx*3+1] = g_Apad[1][gi][gj+128];
        s_a[idx*3+2] = g_Apad[2][gi][gj+128];
    }
    __syncthreads();

    int x = X0 + ty, y = Y0 + tx;
    float px = (float)x + 0.5f;
    float py = (float)y + 0.5f;
    float acc0 = 0.0f, acc1 = 0.0f, acc2 = 0.0f;
    const float inv = 1.0f / 1.69f;   // 1/(4*sigma^2)

    #pragma unroll
    for (int dx = -5; dx <= 5; ++dx) {
        int si = ty + 5 - dx;
        #pragma unroll
        for (int dy = -5; dy <= 5; ++dy) {
            int sj = tx + 5 - dy;
            int base = si*26 + sj;
            const float* mu = s_mu + base*6;
            const float* av = s_a + base*3;
            #pragma unroll
            for (int c = 0; c < 3; c++) {
                float ax = 1.15f - fabsf(px - mu[2*c + 0]);
                float ay = 1.15f - fabsf(py - mu[2*c + 1]);
                ax = fminf(fmaxf(ax, 0.0f), 1.0f);
                ay = fminf(fmaxf(ay, 0.0f), 1.0f);
                float area = ax * ay * inv;
                if (c == 0) acc0 = fmaf(av[0], area, acc0);
                else if (c == 1) acc1 = fmaf(av[1], area, acc1);
                else acc2 = fmaf(av[2], area, acc2);
            }
        }
    }
    out[(x*256+y)*3 + 0] = acc0;
    out[(x*256+y)*3 + 1] = acc1;
    out[(x*256+y)*3 + 2] = acc2;
}

// ---------------- launch ----------------
extern "C" void kernel_launch(void* const* d_in, const int* in_sizes, int n_in,
                              void* d_out, int out_size) {
    const float* A = (const float*)d_in[0];
    const float* R = (const float*)d_in[1];
    const float* r = (const float*)d_in[2];
    const float* m = (const float*)d_in[3];
    const float* s = (const float*)d_in[4];
    const float* h = (const float*)d_in[5];
    const float* a = (const float*)d_in[6];
    const float* b = (const float*)d_in[7];
    const float* w = (const float*)d_in[8];
    float* out = (float*)d_out;

    prep_kernel<<<256, 256>>>(A, R, r);
    kbuild_kernel<<<dim3(KROWS, NK), 256>>>(R, r, a, b, w);
    ksum_kernel<<<NK, 256>>>();
    convp_kernel<<<dim3(NK, MAXCH, 32), dim3(64, 2)>>>();
    combine_kernel<<<256, 256>>>(m, s, h);
    sobelmu_kernel<<<256, 256>>>(A);
    gather_kernel<<<dim3(16, 16), 256>>>(out);
}

// round 9
// speedup vs baseline: 3.3385x; 1.9566x over previous
#include <cuda_runtime.h>
#include <math.h>

#define NK 10
#define NIMG 13   // images 0..2 = A channels, 3..12 = kernels

// ---------------- scratch (static device globals; no allocation) ----------------
__device__ __align__(16) float2 g_cA[NIMG * 65536];
__device__ __align__(16) float2 g_cB[NIMG * 65536];
__device__ float2 g_tw[256];            // tw[Ns+k] = exp(-i*pi*k/Ns)
__device__ float  g_Asum[256][256];
__device__ double g_part[NK][256];
__device__ double g_ksum[NK];
__device__ __align__(16) float g_U3[3][256][256];
__device__ __align__(16) float g_mu[256*256*6];

__constant__ int c_C0[NK]  = {0,0,0,1,1,1,2,2,2,0};
__constant__ int c_grp[NK] = {0,0,0,1,1,1,2,2,2,0};

// ---------------- 1. prep: A -> complex images, Asum, twiddle table ----------------
__global__ void prep_kernel(const float* __restrict__ A) {
    int x = blockIdx.x, y = threadIdx.x;
    float a0 = A[(x*256+y)*3+0];
    float a1 = A[(x*256+y)*3+1];
    float a2 = A[(x*256+y)*3+2];
    g_Asum[x][y] = a0 + a1 + a2;
    int idx = x*256 + y;
    g_cA[0*65536 + idx] = make_float2(a0, 0.f);
    g_cA[1*65536 + idx] = make_float2(a1, 0.f);
    g_cA[2*65536 + idx] = make_float2(a2, 0.f);
    if (x == 0) {
        if (y == 0) {
            g_tw[0] = make_float2(1.f, 0.f);
        } else {
            int p  = 31 - __clz(y);      // floor(log2(y))
            int Ns = 1 << p;
            int kk = y - Ns;
            double ang = -M_PI * (double)kk / (double)Ns;
            g_tw[y] = make_float2((float)cos(ang), (float)sin(ang));
        }
    }
}

// ---------------- 2. build kernels at wrapped coords (= fftshift) + row sums ------
__global__ void kbuild_kernel(const float* __restrict__ R,
                              const float* __restrict__ r,
                              const float* __restrict__ a,
                              const float* __restrict__ b,
                              const float* __restrict__ w) {
    int i = blockIdx.x;   // x index (wrapped dx)
    int k = blockIdx.y;
    int j = threadIdx.x;  // y index (wrapped dy)
    float S = (R[0] + 15.0f) * r[k];
    float fdx = (i < 128) ? (float)i : (float)(i - 256);
    float fdy = (j < 128) ? (float)j : (float)(j - 256);
    float D  = sqrtf(fdx*fdx + fdy*fdy);
    float Dk = D / S;
    float val = 0.0f;
    if (Dk < 2.9f) {   // reference's fp32 tanh saturates to sig==0 past ~2.8
        float ker = 0.0f;
        #pragma unroll
        for (int t = 0; t < 3; t++) {
            float d = Dk - a[k*3+t];
            ker += b[k*3+t] * expf(-d*d / w[k*3+t]);
        }
        float sig = 0.5f * (tanhf(-(Dk - 1.0f) * 5.0f) + 1.0f);
        val = sig * ker;
    }
    g_cA[(3+k)*65536 + i*256 + j] = make_float2(val, 0.f);

    __shared__ double sd[256];
    sd[j] = (double)val;
    __syncthreads();
    for (int s = 128; s > 0; s >>= 1) {
        if (j < s) sd[j] += sd[j + s];
        __syncthreads();
    }
    if (j == 0) g_part[k][i] = sd[0];
}

// ---------------- 3. reduce row sums -> ksum (deterministic) ----------------
__global__ void ksum_kernel() {
    int k = blockIdx.x, j = threadIdx.x;
    __shared__ double sd[256];
    sd[j] = g_part[k][j];
    __syncthreads();
    for (int s = 128; s > 0; s >>= 1) {
        if (j < s) sd[j] += sd[j + s];
        __syncthreads();
    }
    if (j == 0) g_ksum[k] = sd[0];
}

// ---------------- 4. batched 256-pt Stockham FFT pass (writes transposed) -------
// DIR=0: g_cA -> g_cB ; DIR=1: g_cB -> g_cA. Two passes = natural-order 2D FFT.
template <int DIR>
__global__ void __launch_bounds__(128) fft_pass() {
    __shared__ float2 sbuf[2][256];
    int row = blockIdx.x;
    int img = blockIdx.y;
    int t   = threadIdx.x;   // 0..127

    const float2* __restrict__ in = DIR ? g_cB : g_cA;
    float2* __restrict__ out      = DIR ? g_cA : g_cB;

    const float2* src = in + (img << 16) + (row << 8);
    sbuf[0][t]       = src[t];
    sbuf[0][t + 128] = src[t + 128];
    __syncthreads();

    #pragma unroll
    for (int p = 0; p < 8; p++) {
        int Ns = 1 << p;
        float2* X = sbuf[p & 1];
        float2* Y = sbuf[(p + 1) & 1];
        int kk = t & (Ns - 1);
        float2 a = X[t];
        float2 b = X[t + 128];
        float2 w = g_tw[Ns + kk];
        float br = b.x*w.x - b.y*w.y;
        float bi = b.x*w.y + b.y*w.x;
        int idxD = ((t >> p) << (p + 1)) + kk;
        Y[idxD]      = make_float2(a.x + br, a.y + bi);
        Y[idxD + Ns] = make_float2(a.x - br, a.y - bi);
        __syncthreads();
    }

    float2* X = sbuf[0];   // after 8 stages result is back in buffer 0
    float2* dst = out + (img << 16);
    dst[(t << 8) + row]         = X[t];          // transposed write
    dst[((t + 128) << 8) + row] = X[t + 128];
}

// ---------------- 5. pointwise multiply + conj + scale (prepares inverse) -------
// P = fK * fA[C0k]; store conj(P) / (65536 * ksum). Then real(fft2(that)) = U.
__global__ void mult_kernel() {
    int k   = blockIdx.y;
    int idx = blockIdx.x * 256 + threadIdx.x;
    float2 fk = g_cA[(3+k)*65536 + idx];
    float2 fa = g_cA[c_C0[k]*65536 + idx];
    float  s  = (float)(1.0 / (65536.0 * g_ksum[k]));
    float pr = fk.x*fa.x - fk.y*fa.y;
    float pi = fk.x*fa.y + fk.y*fa.x;
    g_cB[k*65536 + idx] = make_float2(pr * s, -pi * s);
}

// ---------------- 6. growth + channel-group sums ----------------
__global__ void combine_kernel(const float* __restrict__ m,
                               const float* __restrict__ s,
                               const float* __restrict__ h) {
    int x = blockIdx.x, y = threadIdx.x;
    int idx = x*256 + y;
    float u0 = 0.f, u1 = 0.f, u2 = 0.f;
    #pragma unroll
    for (int k = 0; k < NK; k++) {
        float U  = g_cB[k*65536 + idx].x;     // real(ifft2(fK*fA)) (already scaled)
        float gg = (U - m[k]) / s[k];
        float gr = (expf(-0.5f * gg * gg) * 2.0f - 1.0f) * h[k];
        int grp = c_grp[k];
        if (grp == 0) u0 += gr;
        else if (grp == 1) u1 += gr;
        else u2 += gr;
    }
    g_U3[0][x][y] = u0;
    g_U3[1][x][y] = u1;
    g_U3[2][x][y] = u2;
}

// ---------------- 7. sobel + flow F + mu ----------------
__device__ __forceinline__ float padv(const float* p, int xx, int yy) {
    return (xx >= 0 && xx < 256 && yy >= 0 && yy < 256) ? p[xx*256 + yy] : 0.0f;
}

__global__ void sobelmu_kernel(const float* __restrict__ A) {
    int x = blockIdx.x, y = threadIdx.x;
    const float* As = &g_Asum[0][0];
    float nA0 = (padv(As,x-1,y-1) + 2.0f*padv(As,x-1,y) + padv(As,x-1,y+1))
              - (padv(As,x+1,y-1) + 2.0f*padv(As,x+1,y) + padv(As,x+1,y+1));
    float nA1 = (padv(As,x-1,y-1) + 2.0f*padv(As,x,y-1) + padv(As,x+1,y-1))
              - (padv(As,x-1,y+1) + 2.0f*padv(As,x,y+1) + padv(As,x+1,y+1));

    float px = (float)x + 0.5f;
    float py = (float)y + 0.5f;
    #pragma unroll
    for (int c = 0; c < 3; c++) {
        const float* Uc = &g_U3[c][0][0];
        float nU0 = (padv(Uc,x-1,y-1) + 2.0f*padv(Uc,x-1,y) + padv(Uc,x-1,y+1))
                  - (padv(Uc,x+1,y-1) + 2.0f*padv(Uc,x+1,y) + padv(Uc,x+1,y+1));
        float nU1 = (padv(Uc,x-1,y-1) + 2.0f*padv(Uc,x,y-1) + padv(Uc,x+1,y-1))
                  - (padv(Uc,x-1,y+1) + 2.0f*padv(Uc,x,y+1) + padv(Uc,x+1,y+1));
        float Ac = A[(x*256+y)*3 + c];
        float al = Ac * (1.0f/3.0f);
        al = al * al;
        al = fminf(al, 1.0f);
        float F0 = nU0 * (1.0f - al) - nA0 * al;
        float F1 = nU1 * (1.0f - al) - nA1 * al;
        float d0 = fminf(fmaxf(0.2f * F0, -4.35f), 4.35f);
        float d1 = fminf(fmaxf(0.2f * F1, -4.35f), 4.35f);
        float mux = fminf(fmaxf(px + d0, 0.65f), 255.35f);
        float muy = fminf(fmaxf(py + d1, 0.65f), 255.35f);
        g_mu[(x*256+y)*6 + c*2 + 0] = mux;
        g_mu[(x*256+y)*6 + c*2 + 1] = muy;
    }
}

// ---------------- 8. reintegration tracking (smem-tiled gather) ----------------
__global__ void __launch_bounds__(256) gather_kernel(const float* __restrict__ A,
                                                     float* __restrict__ out) {
    __shared__ float s_mu[26*26*6];
    __shared__ float s_a[26*26*3];
    int tid = threadIdx.x;
    int tx = tid & 15;    // y within tile
    int ty = tid >> 4;    // x within tile
    int X0 = blockIdx.x * 16, Y0 = blockIdx.y * 16;

    for (int idx = tid; idx < 26*26; idx += 256) {
        int ii = idx / 26, jj = idx - ii*26;
        int gi = (X0 - 5 + ii) & 255;
        int gj = (Y0 - 5 + jj) & 255;
        const float2* mu = (const float2*)(g_mu + (gi*256 + gj)*6);
        float2* d = (float2*)(s_mu + idx*6);
        d[0] = mu[0]; d[1] = mu[1]; d[2] = mu[2];
        s_a[idx*3+0] = A[(gi*256+gj)*3+0];
        s_a[idx*3+1] = A[(gi*256+gj)*3+1];
        s_a[idx*3+2] = A[(gi*256+gj)*3+2];
    }
    __syncthreads();

    int x = X0 + ty, y = Y0 + tx;
    float px = (float)x + 0.5f;
    float py = (float)y + 0.5f;
    float acc0 = 0.0f, acc1 = 0.0f, acc2 = 0.0f;
    const float inv = 1.0f / 1.69f;   // 1/(4*sigma^2)

    #pragma unroll
    for (int dx = -5; dx <= 5; ++dx) {
        int si = ty + 5 - dx;
        #pragma unroll
        for (int dy = -5; dy <= 5; ++dy) {
            int sj = tx + 5 - dy;
            int base = si*26 + sj;
            const float* mu = s_mu + base*6;
            const float* av = s_a + base*3;
            #pragma unroll
            for (int c = 0; c < 3; c++) {
                float ax = 1.15f - fabsf(px - mu[2*c + 0]);
                float ay = 1.15f - fabsf(py - mu[2*c + 1]);
                ax = fminf(fmaxf(ax, 0.0f), 1.0f);
                ay = fminf(fmaxf(ay, 0.0f), 1.0f);
                float area = ax * ay * inv;
                if (c == 0) acc0 = fmaf(av[0], area, acc0);
                else if (c == 1) acc1 = fmaf(av[1], area, acc1);
                else acc2 = fmaf(av[2], area, acc2);
            }
        }
    }
    out[(x*256+y)*3 + 0] = acc0;
    out[(x*256+y)*3 + 1] = acc1;
    out[(x*256+y)*3 + 2] = acc2;
}

// ---------------- launch ----------------
extern "C" void kernel_launch(void* const* d_in, const int* in_sizes, int n_in,
                              void* d_out, int out_size) {
    const float* A = (const float*)d_in[0];
    const float* R = (const float*)d_in[1];
    const float* r = (const float*)d_in[2];
    const float* m = (const float*)d_in[3];
    const float* s = (const float*)d_in[4];
    const float* h = (const float*)d_in[5];
    const float* a = (const float*)d_in[6];
    const float* b = (const float*)d_in[7];
    const float* w = (const float*)d_in[8];
    float* out = (float*)d_out;

    prep_kernel<<<256, 256>>>(A);
    kbuild_kernel<<<dim3(256, NK), 256>>>(R, r, a, b, w);
    ksum_kernel<<<NK, 256>>>();
    // forward 2D FFT of all 13 images (two transposing passes)
    fft_pass<0><<<dim3(256, NIMG), 128>>>();
    fft_pass<1><<<dim3(256, NIMG), 128>>>();
    // pointwise multiply + conj + scale
    mult_kernel<<<dim3(256, NK), 256>>>();
    // inverse 2D FFT of the 10 products (fwd transform of conj)
    fft_pass<1><<<dim3(256, NK), 128>>>();
    fft_pass<0><<<dim3(256, NK), 128>>>();
    combine_kernel<<<256, 256>>>(m, s, h);
    sobelmu_kernel<<<256, 256>>>(A);
    gather_kernel<<<dim3(16, 16), 256>>>(A, out);
}

// round 10
// speedup vs baseline: 4.7038x; 1.4089x over previous
#include <cuda_runtime.h>
#include <math.h>

#define NK 10
#define NIMG 8    // 0..2 = A channels, 3..7 = packed kernel pairs

// ---------------- scratch (static device globals; no allocation) ----------------
__device__ __align__(16) float2 g_cA[NIMG * 65536];
__device__ __align__(16) float2 g_cB[NIMG * 65536];
__device__ float2 g_tw[128];            // tw[Ns+k] = exp(-i*pi*k/(2*Ns)), Ns in {1,4,16,64}
__device__ float  g_Asum[256][256];
__device__ double g_part[NK][256];
__device__ double g_ksum[NK];
__device__ __align__(16) float g_U3[3][256][256];
__device__ __align__(16) float g_mu[256*256*6];

__constant__ int c_grp[NK]   = {0,0,0,1,1,1,2,2,2,0};
__constant__ int c_pairA[5]  = {0,0,1,2,2};   // C0[2j]
__constant__ int c_pairB[5]  = {0,1,1,2,0};   // C0[2j+1]

__device__ __forceinline__ float2 cadd(float2 a, float2 b){ return make_float2(a.x+b.x, a.y+b.y); }
__device__ __forceinline__ float2 csub(float2 a, float2 b){ return make_float2(a.x-b.x, a.y-b.y); }
__device__ __forceinline__ float2 cmul(float2 a, float2 b){
    return make_float2(a.x*b.x - a.y*b.y, a.x*b.y + a.y*b.x);
}

// ---------------- 1. prep: A -> complex images, Asum, radix-4 twiddles ----------------
__global__ void prep_kernel(const float* __restrict__ A) {
    int x = blockIdx.x, y = threadIdx.x;
    float a0 = A[(x*256+y)*3+0];
    float a1 = A[(x*256+y)*3+1];
    float a2 = A[(x*256+y)*3+2];
    g_Asum[x][y] = a0 + a1 + a2;
    int idx = x*256 + y;
    g_cA[0*65536 + idx] = make_float2(a0, 0.f);
    g_cA[1*65536 + idx] = make_float2(a1, 0.f);
    g_cA[2*65536 + idx] = make_float2(a2, 0.f);
    if (x == 0 && y < 128) {
        if (y == 0) {
            g_tw[0] = make_float2(1.f, 0.f);
        } else {
            int p  = 31 - __clz(y);
            int Ns = 1 << p;
            int kk = y - Ns;
            double ang = -M_PI * (double)kk / (2.0 * (double)Ns);
            g_tw[y] = make_float2((float)cos(ang), (float)sin(ang));
        }
    }
}

// ---------------- 2. build packed kernel pairs (K2p + i*K2p+1) + row sums ------
__device__ __forceinline__ float kval(float Dk,
                                      const float* a, const float* b, const float* w, int k) {
    float val = 0.0f;
    if (Dk < 2.9f) {   // fp32 tanh saturates -> sig exactly 0 past ~2.81
        float ker = 0.0f;
        #pragma unroll
        for (int t = 0; t < 3; t++) {
            float d = Dk - a[k*3+t];
            ker += b[k*3+t] * expf(-d*d / w[k*3+t]);
        }
        float sig = 0.5f * (tanhf(-(Dk - 1.0f) * 5.0f) + 1.0f);
        val = sig * ker;
    }
    return val;
}

__global__ void kbuild_kernel(const float* __restrict__ R,
                              const float* __restrict__ r,
                              const float* __restrict__ a,
                              const float* __restrict__ b,
                              const float* __restrict__ w) {
    int i = blockIdx.x;   // wrapped dx index
    int p = blockIdx.y;   // kernel pair 0..4
    int j = threadIdx.x;  // wrapped dy index
    int k0 = 2*p, k1 = 2*p + 1;
    float fdx = (i < 128) ? (float)i : (float)(i - 256);
    float fdy = (j < 128) ? (float)j : (float)(j - 256);
    float D = sqrtf(fdx*fdx + fdy*fdy);
    float Rv = R[0] + 15.0f;
    float v0 = kval(D / (Rv * r[k0]), a, b, w, k0);
    float v1 = kval(D / (Rv * r[k1]), a, b, w, k1);
    g_cA[(3+p)*65536 + i*256 + j] = make_float2(v0, v1);

    __shared__ double sd[256];
    sd[j] = (double)v0;
    __syncthreads();
    for (int s = 128; s > 0; s >>= 1) {
        if (j < s) sd[j] += sd[j + s];
        __syncthreads();
    }
    if (j == 0) g_part[k0][i] = sd[0];
    __syncthreads();
    sd[j] = (double)v1;
    __syncthreads();
    for (int s = 128; s > 0; s >>= 1) {
        if (j < s) sd[j] += sd[j + s];
        __syncthreads();
    }
    if (j == 0) g_part[k1][i] = sd[0];
}

// ---------------- 3. reduce row sums -> ksum (deterministic) ----------------
__global__ void ksum_kernel() {
    int k = blockIdx.x, j = threadIdx.x;
    __shared__ double sd[256];
    sd[j] = g_part[k][j];
    __syncthreads();
    for (int s = 128; s > 0; s >>= 1) {
        if (j < s) sd[j] += sd[j + s];
        __syncthreads();
    }
    if (j == 0) g_ksum[k] = sd[0];
}

// ---------------- 4. radix-4 Stockham 256-pt FFT pass, 4 rows/block --------------
// MODE 0: g_cA -> g_cB (forward pass 1)
// MODE 1: g_cB -> g_cA (forward pass 2 / inverse pass 2)
// MODE 2: fused multiply+conj: read spectra pairs from g_cA, FFT, -> g_cB (inverse pass 1)
// Every pass writes transposed; two passes restore natural order.
template <int MODE>
__global__ void __launch_bounds__(256) fft4_pass() {
    __shared__ float2 sb[2][4][258];   // +2 pad: bank-conflict-free transposed store
    int tx  = threadIdx.x;   // 0..63
    int ty  = threadIdx.y;   // 0..3
    int rb  = blockIdx.x * 4;
    int row = rb + ty;
    int img = blockIdx.y;

    float2* B0 = sb[0][ty];

    if (MODE == 2) {
        // conj(Q), Q = fK_a*fA_a + i*fK_b*fA_b ; fK_a = Re(Kpack), fK_b = Im(Kpack)
        const float2* Kp = g_cA + (3+img)*65536 + row*256;
        const float2* Fa = g_cA + c_pairA[img]*65536 + row*256;
        const float2* Fb = g_cA + c_pairB[img]*65536 + row*256;
        #pragma unroll
        for (int i = 0; i < 4; i++) {
            int q = tx + i*64;
            float2 kp = Kp[q];
            float2 fa = Fa[q];
            float2 fb = Fb[q];
            B0[q] = make_float2(kp.x*fa.x - kp.y*fb.y, -(kp.x*fa.y) - kp.y*fb.x);
        }
    } else {
        const float2* src = (MODE == 0 ? g_cA : g_cB) + img*65536 + row*256;
        #pragma unroll
        for (int i = 0; i < 4; i++) B0[tx + i*64] = src[tx + i*64];
    }
    __syncthreads();

    #pragma unroll
    for (int p = 0; p < 4; p++) {
        float2* X = sb[p & 1][ty];
        float2* Y = sb[(p + 1) & 1][ty];
        int Ns = 1 << (2*p);
        int kk = tx & (Ns - 1);
        float2 av = X[tx];
        float2 bv = X[tx + 64];
        float2 cv = X[tx + 128];
        float2 dv = X[tx + 192];
        float2 w1 = g_tw[Ns + kk];
        float2 w2 = cmul(w1, w1);
        float2 w3 = cmul(w2, w1);
        bv = cmul(bv, w1); cv = cmul(cv, w2); dv = cmul(dv, w3);
        float2 t0 = cadd(av, cv), t1 = csub(av, cv), t2 = cadd(bv, dv);
        float2 bd = csub(bv, dv);
        float2 t3 = make_float2(bd.y, -bd.x);      // -i*(b-d)
        int o = ((tx >> (2*p)) << (2*p + 2)) + kk;
        Y[o]        = cadd(t0, t2);
        Y[o + Ns]   = cadd(t1, t3);
        Y[o + 2*Ns] = csub(t0, t2);
        Y[o + 3*Ns] = csub(t1, t3);
        __syncthreads();
    }

    // cooperative transposed store from sb[0]
    float2* dst = (MODE == 1 ? g_cA : g_cB) + img*65536;
    int tid = ty*64 + tx;
    #pragma unroll
    for (int i = 0; i < 4; i++) {
        int e = tid + i*256;
        int q = e >> 2, rr = e & 3;
        dst[q*256 + rb + rr] = sb[0][rr][q];
    }
}

// ---------------- 5. growth + channel-group sums ----------------
// Packed inverse: Z_j holds (U_2j, -U_2j+1) * 65536 * ksum (unnormalized).
__global__ void combine_kernel(const float* __restrict__ m,
                               const float* __restrict__ s,
                               const float* __restrict__ h) {
    int x = blockIdx.x, y = threadIdx.x;
    int idx = x*256 + y;
    float u0 = 0.f, u1 = 0.f, u2 = 0.f;
    #pragma unroll
    for (int j = 0; j < 5; j++) {
        float2 z = g_cA[j*65536 + idx];
        #pragma unroll
        for (int q = 0; q < 2; q++) {
            int k = 2*j + q;
            float inv = (float)(1.0 / (65536.0 * g_ksum[k]));
            float U = (q == 0 ? z.x : -z.y) * inv;
            float gg = (U - m[k]) / s[k];
            float gr = (expf(-0.5f * gg * gg) * 2.0f - 1.0f) * h[k];
            int grp = c_grp[k];
            if (grp == 0) u0 += gr;
            else if (grp == 1) u1 += gr;
            else u2 += gr;
        }
    }
    g_U3[0][x][y] = u0;
    g_U3[1][x][y] = u1;
    g_U3[2][x][y] = u2;
}

// ---------------- 6. sobel + flow F + mu ----------------
__device__ __forceinline__ float padv(const float* p, int xx, int yy) {
    return (xx >= 0 && xx < 256 && yy >= 0 && yy < 256) ? p[xx*256 + yy] : 0.0f;
}

__global__ void sobelmu_kernel(const float* __restrict__ A) {
    int x = blockIdx.x, y = threadIdx.x;
    const float* As = &g_Asum[0][0];
    float nA0 = (padv(As,x-1,y-1) + 2.0f*padv(As,x-1,y) + padv(As,x-1,y+1))
              - (padv(As,x+1,y-1) + 2.0f*padv(As,x+1,y) + padv(As,x+1,y+1));
    float nA1 = (padv(As,x-1,y-1) + 2.0f*padv(As,x,y-1) + padv(As,x+1,y-1))
              - (padv(As,x-1,y+1) + 2.0f*padv(As,x,y+1) + padv(As,x+1,y+1));

    float px = (float)x + 0.5f;
    float py = (float)y + 0.5f;
    #pragma unroll
    for (int c = 0; c < 3; c++) {
        const float* Uc = &g_U3[c][0][0];
        float nU0 = (padv(Uc,x-1,y-1) + 2.0f*padv(Uc,x-1,y) + padv(Uc,x-1,y+1))
                  - (padv(Uc,x+1,y-1) + 2.0f*padv(Uc,x+1,y) + padv(Uc,x+1,y+1));
        float nU1 = (padv(Uc,x-1,y-1) + 2.0f*padv(Uc,x,y-1) + padv(Uc,x+1,y-1))
                  - (padv(Uc,x-1,y+1) + 2.0f*padv(Uc,x,y+1) + padv(Uc,x+1,y+1));
        float Ac = A[(x*256+y)*3 + c];
        float al = Ac * (1.0f/3.0f);
        al = al * al;
        al = fminf(al, 1.0f);
        float F0 = nU0 * (1.0f - al) - nA0 * al;
        float F1 = nU1 * (1.0f - al) - nA1 * al;
        float d0 = fminf(fmaxf(0.2f * F0, -4.35f), 4.35f);
        float d1 = fminf(fmaxf(0.2f * F1, -4.35f), 4.35f);
        float mux = fminf(fmaxf(px + d0, 0.65f), 255.35f);
        float muy = fminf(fmaxf(py + d1, 0.65f), 255.35f);
        g_mu[(x*256+y)*6 + c*2 + 0] = mux;
        g_mu[(x*256+y)*6 + c*2 + 1] = muy;
    }
}

// ---------------- 7. reintegration tracking (smem-tiled gather) ----------------
__global__ void __launch_bounds__(256) gather_kernel(const float* __restrict__ A,
                                                     float* __restrict__ out) {
    __shared__ float s_mu[26*26*6];
    __shared__ float s_a[26*26*3];
    int tid = threadIdx.x;
    int tx = tid & 15;
    int ty = tid >> 4;
    int X0 = blockIdx.x * 16, Y0 = blockIdx.y * 16;

    for (int idx = tid; idx < 26*26; idx += 256) {
        int ii = idx / 26, jj = idx - ii*26;
        int gi = (X0 - 5 + ii) & 255;
        int gj = (Y0 - 5 + jj) & 255;
        const float2* mu = (const float2*)(g_mu + (gi*256 + gj)*6);
        float2* d = (float2*)(s_mu + idx*6);
        d[0] = mu[0]; d[1] = mu[1]; d[2] = mu[2];
        s_a[idx*3+0] = A[(gi*256+gj)*3+0];
        s_a[idx*3+1] = A[(gi*256+gj)*3+1];
        s_a[idx*3+2] = A[(gi*256+gj)*3+2];
    }
    __syncthreads();

    int x = X0 + ty, y = Y0 + tx;
    float px = (float)x + 0.5f;
    float py = (float)y + 0.5f;
    float acc0 = 0.0f, acc1 = 0.0f, acc2 = 0.0f;
    const float inv = 1.0f / 1.69f;

    #pragma unroll
    for (int dx = -5; dx <= 5; ++dx) {
        int si = ty + 5 - dx;
        #pragma unroll
        for (int dy = -5; dy <= 5; ++dy) {
            int sj = tx + 5 - dy;
            int base = si*26 + sj;
            const float* mu = s_mu + base*6;
            const float* av = s_a + base*3;
            #pragma unroll
            for (int c = 0; c < 3; c++) {
                float ax = 1.15f - fabsf(px - mu[2*c + 0]);
                float ay = 1.15f - fabsf(py - mu[2*c + 1]);
                ax = fminf(fmaxf(ax, 0.0f), 1.0f);
                ay = fminf(fmaxf(ay, 0.0f), 1.0f);
                float area = ax * ay * inv;
                if (c == 0) acc0 = fmaf(av[0], area, acc0);
                else if (c == 1) acc1 = fmaf(av[1], area, acc1);
                else acc2 = fmaf(av[2], area, acc2);
            }
        }
    }
    out[(x*256+y)*3 + 0] = acc0;
    out[(x*256+y)*3 + 1] = acc1;
    out[(x*256+y)*3 + 2] = acc2;
}

// ---------------- launch ----------------
extern "C" void kernel_launch(void* const* d_in, const int* in_sizes, int n_in,
                              void* d_out, int out_size) {
    const float* A = (const float*)d_in[0];
    const float* R = (const float*)d_in[1];
    const float* r = (const float*)d_in[2];
    const float* m = (const float*)d_in[3];
    const float* s = (const float*)d_in[4];
    const float* h = (const float*)d_in[5];
    const float* a = (const float*)d_in[6];
    const float* b = (const float*)d_in[7];
    const float* w = (const float*)d_in[8];
    float* out = (float*)d_out;

    prep_kernel<<<256, 256>>>(A);
    kbuild_kernel<<<dim3(256, 5), 256>>>(R, r, a, b, w);
    ksum_kernel<<<NK, 256>>>();
    // forward 2D FFT of 8 images (3 A + 5 packed kernel pairs)
    fft4_pass<0><<<dim3(64, NIMG), dim3(64, 4)>>>();
    fft4_pass<1><<<dim3(64, NIMG), dim3(64, 4)>>>();
    // inverse of 5 packed products (mult+conj fused into pass 1)
    fft4_pass<2><<<dim3(64, 5), dim3(64, 4)>>>();
    fft4_pass<1><<<dim3(64, 5), dim3(64, 4)>>>();
    combine_kernel<<<256, 256>>>(m, s, h);
    sobelmu_kernel<<<256, 256>>>(A);
    gather_kernel<<<dim3(16, 16), 256>>>(A, out);
}